// round 8
// baseline (speedup 1.0000x reference)
#include <cuda_runtime.h>
#include <cuda_fp16.h>
#include <math.h>

#define NB     32
#define NL     2048
#define ND     512
#define NDFF   256
#define NBLK   6
#define GROUP  16                 // batches per L2-resident group
#define NGROUP (NB / GROUP)       // 2
#define FEPS   1e-6f
#define LCHUNK 64
#define NCHUNK (NL / LCHUNK)      // 32

// ---------------- device scratch (no allocations allowed) ----------------
__device__ float  g_q[NB * ND];                    // evolving query (all batches)
__device__ float  g_scores[NB * NL];               // raw scores (global batch index)
__device__ float  g_s_all[NBLK][NB * NL];          // softmax probs per block
__device__ float  g_Apart[NB * NCHUNK * ND];       // partial attention outputs
__device__ __half g_kh[(size_t)GROUP * NL * ND];   // fp16 K scratch, 32MB (L2-resident)
__device__ __half g_vh[(size_t)GROUP * NL * ND];   // fp16 V scratch, 32MB (L2-resident)

// ---------------- helpers ----------------
__device__ __forceinline__ float block_sum_512(float v, float* red) {
    #pragma unroll
    for (int o = 16; o; o >>= 1) v += __shfl_xor_sync(0xffffffffu, v, o);
    int w = threadIdx.x >> 5;
    if ((threadIdx.x & 31) == 0) red[w] = v;
    __syncthreads();
    if (threadIdx.x < 16) {
        float t = red[threadIdx.x];
        #pragma unroll
        for (int o = 8; o; o >>= 1) t += __shfl_xor_sync(0xffffu, t, o);
        if (threadIdx.x == 0) red[0] = t;
    }
    __syncthreads();
    float r = red[0];
    __syncthreads();
    return r;
}

__device__ __forceinline__ float hdot8(uint4 kv, float4 q0, float4 q1) {
    float2 f0 = __half22float2(*reinterpret_cast<__half2*>(&kv.x));
    float2 f1 = __half22float2(*reinterpret_cast<__half2*>(&kv.y));
    float2 f2 = __half22float2(*reinterpret_cast<__half2*>(&kv.z));
    float2 f3 = __half22float2(*reinterpret_cast<__half2*>(&kv.w));
    float a = 0.f, b = 0.f;
    a = fmaf(f0.x, q0.x, a); b = fmaf(f0.y, q0.y, b);
    a = fmaf(f1.x, q0.z, a); b = fmaf(f1.y, q0.w, b);
    a = fmaf(f2.x, q1.x, a); b = fmaf(f2.y, q1.y, b);
    a = fmaf(f3.x, q1.z, a); b = fmaf(f3.y, q1.w, b);
    return a + b;
}

__device__ __forceinline__ void hfma8(uint4 x, float s, float* a) {
    float2 f0 = __half22float2(*reinterpret_cast<__half2*>(&x.x));
    float2 f1 = __half22float2(*reinterpret_cast<__half2*>(&x.y));
    float2 f2 = __half22float2(*reinterpret_cast<__half2*>(&x.z));
    float2 f3 = __half22float2(*reinterpret_cast<__half2*>(&x.w));
    a[0] = fmaf(s, f0.x, a[0]); a[1] = fmaf(s, f0.y, a[1]);
    a[2] = fmaf(s, f1.x, a[2]); a[3] = fmaf(s, f1.y, a[3]);
    a[4] = fmaf(s, f2.x, a[4]); a[5] = fmaf(s, f2.y, a[5]);
    a[6] = fmaf(s, f3.x, a[6]); a[7] = fmaf(s, f3.y, a[7]);
}

__device__ __forceinline__ uint4 pack_h8(float4 a, float4 b) {
    uint4 o;
    *reinterpret_cast<__half2*>(&o.x) = __floats2half2_rn(a.x, a.y);
    *reinterpret_cast<__half2*>(&o.y) = __floats2half2_rn(a.z, a.w);
    *reinterpret_cast<__half2*>(&o.z) = __floats2half2_rn(b.x, b.y);
    *reinterpret_cast<__half2*>(&o.w) = __floats2half2_rn(b.z, b.w);
    return o;
}

// ---------------- kernels ----------------
// Per-group convert: fp32 K,V (this group's batches) -> fp16 scratch.
// Also copies this group's q rows into g_q (threads 0..GROUP*ND-1).
__global__ void conv_kernel(const float* __restrict__ k, const float* __restrict__ v,
                            const float* __restrict__ q, int bo) {
    const size_t NG = (size_t)GROUP * NL * ND;        // elems per tensor per group
    size_t i = (size_t)blockIdx.x * blockDim.x + threadIdx.x;   // 0 .. 2*NG/8-1
    if (i < GROUP * ND) g_q[(size_t)bo * ND + i] = q[(size_t)bo * ND + i];
    size_t base = (size_t)bo * NL * ND;
    const float4* src;
    __half* dst;
    size_t off;
    if (i < NG / 8) { src = (const float4*)(k + base); dst = g_kh; off = i; }
    else            { src = (const float4*)(v + base); dst = g_vh; off = i - NG / 8; }
    float4 a = __ldcs(src + off * 2);
    float4 b = __ldcs(src + off * 2 + 1);
    reinterpret_cast<uint4*>(dst)[off] = pack_h8(a, b);
}

// scores for one group: fp16 K from L2 scratch; one warp per row.
__global__ void scoresG_kernel(int bo) {
    int warp = (blockIdx.x * blockDim.x + threadIdx.x) >> 5;   // 0 .. GROUP*NL-1
    int lane = threadIdx.x & 31;
    if (warp >= GROUP * NL) return;
    int gb = warp >> 11;               // batch within group
    int bglob = bo + gb;
    const uint4*  kk = reinterpret_cast<const uint4*>(g_kh + (size_t)warp * ND);
    const float4* q4 = reinterpret_cast<const float4*>(g_q + bglob * ND);

    uint4 kv0 = kk[lane];
    uint4 kv1 = kk[lane + 32];
    float4 q0 = q4[lane * 2],      q1 = q4[lane * 2 + 1];
    float4 q2 = q4[64 + lane * 2], q3 = q4[64 + lane * 2 + 1];

    float acc = hdot8(kv0, q0, q1) + hdot8(kv1, q2, q3);
    #pragma unroll
    for (int o = 16; o; o >>= 1) acc += __shfl_xor_sync(0xffffffffu, acc, o);
    if (lane == 0)
        g_scores[bglob * NL + (warp & (NL - 1))] = acc * 0.04419417382415922f;
}

// softmax over L for one group's batches; writes contiguous g_s_all[blk]
__global__ void softmaxG_kernel(int blk, int bo) {
    int b = bo + blockIdx.x;
    int t = threadIdx.x;            // 512 threads
    __shared__ float red[16];
    const float* sc = g_scores + b * NL;

    float e[NL / 512];
    float m = -INFINITY;
    #pragma unroll
    for (int i = 0; i < NL / 512; i++) {
        e[i] = sc[t + i * 512];
        m = fmaxf(m, e[i]);
    }
    #pragma unroll
    for (int o = 16; o; o >>= 1) m = fmaxf(m, __shfl_xor_sync(0xffffffffu, m, o));
    int w = t >> 5;
    if ((t & 31) == 0) red[w] = m;
    __syncthreads();
    if (t < 16) {
        float x = red[t];
        #pragma unroll
        for (int o = 8; o; o >>= 1) x = fmaxf(x, __shfl_xor_sync(0xffffu, x, o));
        if (t == 0) red[0] = x;
    }
    __syncthreads();
    m = red[0];
    __syncthreads();

    float sum = 0.f;
    #pragma unroll
    for (int i = 0; i < NL / 512; i++) {
        e[i] = expf(e[i] - m);
        sum += e[i];
    }
    float tot = block_sum_512(sum, red);
    float inv = 1.0f / tot;

    #pragma unroll
    for (int i = 0; i < NL / 512; i++) {
        int l = t + i * 512;
        g_s_all[blk][b * NL + l] = e[i] * inv;
    }
}

// apart for one group: fp16 V from L2 scratch.
// 128 threads = (half, col): half = even/odd row of pair, col = uint4 column.
__global__ void apartG_kernel(int blk, int bo) {
    int c  = blockIdx.x;       // 0..NCHUNK-1
    int gb = blockIdx.y;       // 0..GROUP-1
    int b  = bo + gb;
    int t  = threadIdx.x;
    int half = t >> 6;
    int col  = t & 63;

    __shared__ float ss[LCHUNK];
    __shared__ float part[ND];
    if (t < LCHUNK) ss[t] = g_s_all[blk][b * NL + c * LCHUNK + t];
    __syncthreads();

    const uint4* vp = reinterpret_cast<const uint4*>(
        g_vh + ((size_t)gb * NL + (size_t)c * LCHUNK) * ND) + half * 64 + col;

    float a[8] = {0, 0, 0, 0, 0, 0, 0, 0};
    #pragma unroll
    for (int g = 0; g < LCHUNK / 2; g += 8) {
        uint4 x0 = vp[(g + 0) * 128];
        uint4 x1 = vp[(g + 1) * 128];
        uint4 x2 = vp[(g + 2) * 128];
        uint4 x3 = vp[(g + 3) * 128];
        uint4 x4 = vp[(g + 4) * 128];
        uint4 x5 = vp[(g + 5) * 128];
        uint4 x6 = vp[(g + 6) * 128];
        uint4 x7 = vp[(g + 7) * 128];
        hfma8(x0, ss[2 * (g + 0) + half], a);
        hfma8(x1, ss[2 * (g + 1) + half], a);
        hfma8(x2, ss[2 * (g + 2) + half], a);
        hfma8(x3, ss[2 * (g + 3) + half], a);
        hfma8(x4, ss[2 * (g + 4) + half], a);
        hfma8(x5, ss[2 * (g + 5) + half], a);
        hfma8(x6, ss[2 * (g + 6) + half], a);
        hfma8(x7, ss[2 * (g + 7) + half], a);
    }

    if (half == 1) {
        float4* p4 = reinterpret_cast<float4*>(part);
        p4[col * 2]     = make_float4(a[0], a[1], a[2], a[3]);
        p4[col * 2 + 1] = make_float4(a[4], a[5], a[6], a[7]);
    }
    __syncthreads();
    if (half == 0) {
        const float4* p4 = reinterpret_cast<const float4*>(part);
        float4 p0 = p4[col * 2], p1 = p4[col * 2 + 1];
        float4* o4 = reinterpret_cast<float4*>(g_Apart + (b * NCHUNK + c) * ND);
        o4[col * 2]     = make_float4(a[0] + p0.x, a[1] + p0.y, a[2] + p0.z, a[3] + p0.w);
        o4[col * 2 + 1] = make_float4(a[4] + p1.x, a[5] + p1.y, a[6] + p1.z, a[7] + p1.w);
    }
}

// fused tail for one group's batches
__global__ void tailG_kernel(const float* __restrict__ W1, const float* __restrict__ b1,
                             const float* __restrict__ W2, const float* __restrict__ b2,
                             const float* __restrict__ al1, const float* __restrict__ bi1,
                             const float* __restrict__ al2, const float* __restrict__ bi2,
                             float* __restrict__ out, int blk, int bo,
                             int write_out, int out_off) {
    int b = bo + blockIdx.x;
    int d = threadIdx.x;
    __shared__ float red[16];
    __shared__ float sh_q[ND];
    __shared__ float sh_p[ND];
    __shared__ float sh_h[NDFF];

    float x = g_q[b * ND + d];
    #pragma unroll 8
    for (int c = 0; c < NCHUNK; c++) x += g_Apart[(b * NCHUNK + c) * ND + d];

    float mu  = block_sum_512(x, red) * (1.0f / ND);
    float dev = x - mu;
    float var = block_sum_512(dev * dev, red) * (1.0f / (ND - 1));
    float qn1 = al1[blk * ND + d] * dev / (sqrtf(var) + FEPS) + bi1[blk * ND + d];
    sh_q[d] = qn1;
    __syncthreads();

    {
        int j    = d & (NDFF - 1);
        int half = d >> 8;
        const float* w  = W1 + (size_t)blk * ND * NDFF + (size_t)(half * 256) * NDFF + j;
        const float* xq = sh_q + half * 256;
        float c0 = 0.f, c1 = 0.f, c2 = 0.f, c3 = 0.f;
        float c4 = 0.f, c5 = 0.f, c6 = 0.f, c7 = 0.f;
        #pragma unroll 4
        for (int i = 0; i < 256; i += 8) {
            c0 = fmaf(xq[i + 0], __ldg(w + (i + 0) * NDFF), c0);
            c1 = fmaf(xq[i + 1], __ldg(w + (i + 1) * NDFF), c1);
            c2 = fmaf(xq[i + 2], __ldg(w + (i + 2) * NDFF), c2);
            c3 = fmaf(xq[i + 3], __ldg(w + (i + 3) * NDFF), c3);
            c4 = fmaf(xq[i + 4], __ldg(w + (i + 4) * NDFF), c4);
            c5 = fmaf(xq[i + 5], __ldg(w + (i + 5) * NDFF), c5);
            c6 = fmaf(xq[i + 6], __ldg(w + (i + 6) * NDFF), c6);
            c7 = fmaf(xq[i + 7], __ldg(w + (i + 7) * NDFF), c7);
        }
        sh_p[d] = ((c0 + c1) + (c2 + c3)) + ((c4 + c5) + (c6 + c7));
    }
    __syncthreads();
    if (d < NDFF) {
        float hv = sh_p[d] + sh_p[d + 256] + b1[blk * NDFF + d];
        sh_h[d] = fmaxf(hv, 0.f);
    }
    __syncthreads();

    float acc = b2[blk * ND + d];
    {
        const float* w2 = W2 + (size_t)blk * NDFF * ND + d;
        float c0 = 0.f, c1 = 0.f, c2 = 0.f, c3 = 0.f;
        float c4 = 0.f, c5 = 0.f, c6 = 0.f, c7 = 0.f;
        #pragma unroll 4
        for (int j = 0; j < NDFF; j += 8) {
            c0 = fmaf(sh_h[j + 0], __ldg(w2 + (j + 0) * ND), c0);
            c1 = fmaf(sh_h[j + 1], __ldg(w2 + (j + 1) * ND), c1);
            c2 = fmaf(sh_h[j + 2], __ldg(w2 + (j + 2) * ND), c2);
            c3 = fmaf(sh_h[j + 3], __ldg(w2 + (j + 3) * ND), c3);
            c4 = fmaf(sh_h[j + 4], __ldg(w2 + (j + 4) * ND), c4);
            c5 = fmaf(sh_h[j + 5], __ldg(w2 + (j + 5) * ND), c5);
            c6 = fmaf(sh_h[j + 6], __ldg(w2 + (j + 6) * ND), c6);
            c7 = fmaf(sh_h[j + 7], __ldg(w2 + (j + 7) * ND), c7);
        }
        acc += ((c0 + c1) + (c2 + c3)) + ((c4 + c5) + (c6 + c7));
    }
    float x2 = qn1 + acc;

    float mu2  = block_sum_512(x2, red) * (1.0f / ND);
    float dev2 = x2 - mu2;
    float var2 = block_sum_512(dev2 * dev2, red) * (1.0f / (ND - 1));
    float qn2 = al2[blk * ND + d] * dev2 / (sqrtf(var2) + FEPS) + bi2[blk * ND + d];

    g_q[b * ND + d] = qn2;
    if (write_out) out[b * (2 * ND) + out_off + d] = qn2;
}

// final: assemble weights (B, L, NBLK)
__global__ void combine_kernel(float* __restrict__ wout) {
    int i = blockIdx.x * blockDim.x + threadIdx.x;
    if (i >= NB * NL) return;
    float vals[NBLK];
    #pragma unroll
    for (int blk = 0; blk < NBLK; blk++) vals[blk] = g_s_all[blk][i];
    float* o = wout + (size_t)i * NBLK;
    #pragma unroll
    for (int blk = 0; blk < NBLK; blk++) o[blk] = vals[blk];
}

// ---------------- launch ----------------
extern "C" void kernel_launch(void* const* d_in, const int* in_sizes, int n_in,
                              void* d_out, int out_size) {
    const float* q   = (const float*)d_in[0];
    const float* k   = (const float*)d_in[1];
    const float* v   = (const float*)d_in[2];
    const float* W1  = (const float*)d_in[3];
    const float* b1  = (const float*)d_in[4];
    const float* W2  = (const float*)d_in[5];
    const float* b2  = (const float*)d_in[6];
    const float* al1 = (const float*)d_in[7];
    const float* bi1 = (const float*)d_in[8];
    const float* al2 = (const float*)d_in[9];
    const float* bi2 = (const float*)d_in[10];

    float* out_p = (float*)d_out;                 // (32, 1024)
    float* w_p   = (float*)d_out + NB * 2 * ND;   // (32, 2048, 6)

    const unsigned conv_ctas = (unsigned)(2 * ((size_t)GROUP * NL * ND) / 8 / 256);

    for (int g = 0; g < NGROUP; g++) {
        int bo = g * GROUP;
        conv_kernel<<<conv_ctas, 256>>>(k, v, q, bo);
        for (int blk = 0; blk < NBLK; blk++) {
            scoresG_kernel<<<(GROUP * NL * 32) / 256, 256>>>(bo);
            softmaxG_kernel<<<GROUP, 512>>>(blk, bo);
            apartG_kernel<<<dim3(NCHUNK, GROUP), 128>>>(blk, bo);
            int wr = (blk == 2 || blk == 5) ? 1 : 0;
            int off = (blk == 5) ? ND : 0;
            tailG_kernel<<<GROUP, ND>>>(W1, b1, W2, b2, al1, bi1, al2, bi2,
                                        out_p, blk, bo, wr, off);
        }
    }
    combine_kernel<<<(NB * NL + 255) / 256, 256>>>(w_p);
}

// round 9
// speedup vs baseline: 2.3855x; 2.3855x over previous
#include <cuda_runtime.h>
#include <math.h>

#define NB   32
#define NL   2048
#define ND   512
#define NDFF 256
#define NBLK 6
#define FEPS 1e-6f
#define LCHUNK 64
#define NCHUNK (NL / LCHUNK)   // 32

// ---------------- device scratch (no allocations allowed) ----------------
__device__ float g_q[NB * ND];              // evolving query
__device__ float g_scores[NB * NL];         // raw scores
__device__ float g_s[NB * NL];              // softmax probs (contiguous)
__device__ float g_Apart[NB * NCHUNK * ND]; // partial attention outputs

// ---------------- helpers ----------------
__device__ __forceinline__ float block_sum_512(float v, float* red) {
    #pragma unroll
    for (int o = 16; o; o >>= 1) v += __shfl_xor_sync(0xffffffffu, v, o);
    int w = threadIdx.x >> 5;
    if ((threadIdx.x & 31) == 0) red[w] = v;
    __syncthreads();
    if (threadIdx.x < 16) {
        float t = red[threadIdx.x];
        #pragma unroll
        for (int o = 8; o; o >>= 1) t += __shfl_xor_sync(0xffffu, t, o);
        if (threadIdx.x == 0) red[0] = t;
    }
    __syncthreads();
    float r = red[0];
    __syncthreads();
    return r;
}

__device__ __forceinline__ float dot4(float4 a, float4 b, float acc) {
    acc = fmaf(a.x, b.x, acc);
    acc = fmaf(a.y, b.y, acc);
    acc = fmaf(a.z, b.z, acc);
    acc = fmaf(a.w, b.w, acc);
    return acc;
}

// ---------------- kernels ----------------
__global__ void initq_kernel(const float* __restrict__ q) {
    int i = blockIdx.x * blockDim.x + threadIdx.x;
    if (i < NB * ND) g_q[i] = q[i];
}

// scores: TWO rows per warp; 8 x 16B loads in flight per lane
__global__ void scores_kernel(const float* __restrict__ k) {
    int warp = (blockIdx.x * blockDim.x + threadIdx.x) >> 5;  // 0..NB*NL/2-1
    int lane = threadIdx.x & 31;
    if (warp >= NB * NL / 2) return;
    int r0 = warp * 2;            // rows r0, r0+1 (same batch: 2048 rows per b)
    int b = r0 >> 11;
    const float4* kA = reinterpret_cast<const float4*>(k + (size_t)r0 * ND) + lane;
    const float4* kB = reinterpret_cast<const float4*>(k + (size_t)(r0 + 1) * ND) + lane;
    const float4* q4 = reinterpret_cast<const float4*>(g_q + b * ND) + lane;

    float4 a0 = __ldcs(kA + 0);
    float4 a1 = __ldcs(kA + 32);
    float4 a2 = __ldcs(kA + 64);
    float4 a3 = __ldcs(kA + 96);
    float4 b0 = __ldcs(kB + 0);
    float4 b1 = __ldcs(kB + 32);
    float4 b2 = __ldcs(kB + 64);
    float4 b3 = __ldcs(kB + 96);
    float4 q0 = q4[0], q1 = q4[32], q2 = q4[64], q3 = q4[96];

    float accA = 0.f, accB = 0.f;
    accA = dot4(a0, q0, accA); accB = dot4(b0, q0, accB);
    accA = dot4(a1, q1, accA); accB = dot4(b1, q1, accB);
    accA = dot4(a2, q2, accA); accB = dot4(b2, q2, accB);
    accA = dot4(a3, q3, accA); accB = dot4(b3, q3, accB);

    #pragma unroll
    for (int o = 16; o; o >>= 1) {
        accA += __shfl_xor_sync(0xffffffffu, accA, o);
        accB += __shfl_xor_sync(0xffffffffu, accB, o);
    }
    if (lane == 0) {
        const float s = 0.04419417382415922f;   // 1/sqrt(512)
        g_scores[r0]     = accA * s;
        g_scores[r0 + 1] = accB * s;
    }
}

// softmax over L per batch; writes contiguous g_s and strided weights[:, :, blk]
__global__ void softmax_kernel(float* __restrict__ wout, int blk) {
    int b = blockIdx.x;
    int t = threadIdx.x;            // 512 threads
    __shared__ float red[16];
    const float* sc = g_scores + b * NL;

    float e[NL / 512];
    float m = -INFINITY;
    #pragma unroll
    for (int i = 0; i < NL / 512; i++) {
        e[i] = sc[t + i * 512];
        m = fmaxf(m, e[i]);
    }
    #pragma unroll
    for (int o = 16; o; o >>= 1) m = fmaxf(m, __shfl_xor_sync(0xffffffffu, m, o));
    int w = t >> 5;
    if ((t & 31) == 0) red[w] = m;
    __syncthreads();
    if (t < 16) {
        float x = red[t];
        #pragma unroll
        for (int o = 8; o; o >>= 1) x = fmaxf(x, __shfl_xor_sync(0xffffu, x, o));
        if (t == 0) red[0] = x;
    }
    __syncthreads();
    m = red[0];
    __syncthreads();

    float sum = 0.f;
    #pragma unroll
    for (int i = 0; i < NL / 512; i++) {
        e[i] = expf(e[i] - m);
        sum += e[i];
    }
    float tot = block_sum_512(sum, red);
    float inv = 1.0f / tot;

    #pragma unroll
    for (int i = 0; i < NL / 512; i++) {
        int l = t + i * 512;
        float sv = e[i] * inv;
        g_s[b * NL + l] = sv;
        wout[((size_t)b * NL + l) * NBLK + blk] = sv;
    }
}

// partial A: one block per (l-chunk, b); 256 threads = (half, col)
// half = row parity within pair, col = float4 column. 32 loads/thread, 4 accs.
__global__ void apart_kernel(const float* __restrict__ v) {
    int c = blockIdx.x;       // 0..NCHUNK-1
    int b = blockIdx.y;       // 0..31
    int t = threadIdx.x;      // 0..255
    int half = t >> 7;        // 0/1
    int col  = t & 127;       // float4 column (ND/4 = 128)

    __shared__ float ss[LCHUNK];
    __shared__ float part[ND];
    if (t < LCHUNK) ss[t] = g_s[b * NL + c * LCHUNK + t];
    __syncthreads();

    // row stride = 128 float4; thread handles rows (2g + half), g = 0..31
    const float4* vp = reinterpret_cast<const float4*>(
        v + ((size_t)b * NL + (size_t)c * LCHUNK) * ND) + half * 128 + col;

    float4 A0 = {0,0,0,0}, A1 = {0,0,0,0}, A2 = {0,0,0,0}, A3 = {0,0,0,0};
    #pragma unroll
    for (int g = 0; g < LCHUNK / 2; g += 8) {
        float4 v0 = __ldcs(vp + (g + 0) * 256);
        float4 v1 = __ldcs(vp + (g + 1) * 256);
        float4 v2 = __ldcs(vp + (g + 2) * 256);
        float4 v3 = __ldcs(vp + (g + 3) * 256);
        float4 v4 = __ldcs(vp + (g + 4) * 256);
        float4 v5 = __ldcs(vp + (g + 5) * 256);
        float4 v6 = __ldcs(vp + (g + 6) * 256);
        float4 v7 = __ldcs(vp + (g + 7) * 256);
        float s0 = ss[2 * (g + 0) + half];
        float s1 = ss[2 * (g + 1) + half];
        float s2 = ss[2 * (g + 2) + half];
        float s3 = ss[2 * (g + 3) + half];
        float s4 = ss[2 * (g + 4) + half];
        float s5 = ss[2 * (g + 5) + half];
        float s6 = ss[2 * (g + 6) + half];
        float s7 = ss[2 * (g + 7) + half];
        A0.x = fmaf(s0, v0.x, A0.x); A0.y = fmaf(s0, v0.y, A0.y);
        A0.z = fmaf(s0, v0.z, A0.z); A0.w = fmaf(s0, v0.w, A0.w);
        A1.x = fmaf(s1, v1.x, A1.x); A1.y = fmaf(s1, v1.y, A1.y);
        A1.z = fmaf(s1, v1.z, A1.z); A1.w = fmaf(s1, v1.w, A1.w);
        A2.x = fmaf(s2, v2.x, A2.x); A2.y = fmaf(s2, v2.y, A2.y);
        A2.z = fmaf(s2, v2.z, A2.z); A2.w = fmaf(s2, v2.w, A2.w);
        A3.x = fmaf(s3, v3.x, A3.x); A3.y = fmaf(s3, v3.y, A3.y);
        A3.z = fmaf(s3, v3.z, A3.z); A3.w = fmaf(s3, v3.w, A3.w);
        A0.x = fmaf(s4, v4.x, A0.x); A0.y = fmaf(s4, v4.y, A0.y);
        A0.z = fmaf(s4, v4.z, A0.z); A0.w = fmaf(s4, v4.w, A0.w);
        A1.x = fmaf(s5, v5.x, A1.x); A1.y = fmaf(s5, v5.y, A1.y);
        A1.z = fmaf(s5, v5.z, A1.z); A1.w = fmaf(s5, v5.w, A1.w);
        A2.x = fmaf(s6, v6.x, A2.x); A2.y = fmaf(s6, v6.y, A2.y);
        A2.z = fmaf(s6, v6.z, A2.z); A2.w = fmaf(s6, v6.w, A2.w);
        A3.x = fmaf(s7, v7.x, A3.x); A3.y = fmaf(s7, v7.y, A3.y);
        A3.z = fmaf(s7, v7.z, A3.z); A3.w = fmaf(s7, v7.w, A3.w);
    }
    float4 r;
    r.x = (A0.x + A1.x) + (A2.x + A3.x);
    r.y = (A0.y + A1.y) + (A2.y + A3.y);
    r.z = (A0.z + A1.z) + (A2.z + A3.z);
    r.w = (A0.w + A1.w) + (A2.w + A3.w);

    if (half == 1) {
        reinterpret_cast<float4*>(part)[col] = r;
    }
    __syncthreads();
    if (half == 0) {
        float4 p = reinterpret_cast<const float4*>(part)[col];
        float4* o4 = reinterpret_cast<float4*>(g_Apart + (b * NCHUNK + c) * ND);
        o4[col] = make_float4(r.x + p.x, r.y + p.y, r.z + p.z, r.w + p.w);
    }
}

// fused tail: reduce partials + residual + Norm1 + FF(relu) + FF2 + residual + Norm2
__global__ void tail_kernel(const float* __restrict__ W1, const float* __restrict__ b1,
                            const float* __restrict__ W2, const float* __restrict__ b2,
                            const float* __restrict__ al1, const float* __restrict__ bi1,
                            const float* __restrict__ al2, const float* __restrict__ bi2,
                            float* __restrict__ out, int blk, int write_out, int out_off) {
    int b = blockIdx.x;   // 32
    int d = threadIdx.x;  // 512
    __shared__ float red[16];
    __shared__ float sh_q[ND];
    __shared__ float sh_p[ND];
    __shared__ float sh_h[NDFF];

    float x = g_q[b * ND + d];
    #pragma unroll 8
    for (int c = 0; c < NCHUNK; c++) x += g_Apart[(b * NCHUNK + c) * ND + d];

    float mu  = block_sum_512(x, red) * (1.0f / ND);
    float dev = x - mu;
    float var = block_sum_512(dev * dev, red) * (1.0f / (ND - 1));
    float qn1 = al1[blk * ND + d] * dev / (sqrtf(var) + FEPS) + bi1[blk * ND + d];
    sh_q[d] = qn1;
    __syncthreads();

    {
        int j    = d & (NDFF - 1);
        int half = d >> 8;
        const float* w  = W1 + (size_t)blk * ND * NDFF + (size_t)(half * 256) * NDFF + j;
        const float* xq = sh_q + half * 256;
        float c0 = 0.f, c1 = 0.f, c2 = 0.f, c3 = 0.f;
        float c4 = 0.f, c5 = 0.f, c6 = 0.f, c7 = 0.f;
        #pragma unroll 4
        for (int i = 0; i < 256; i += 8) {
            c0 = fmaf(xq[i + 0], __ldg(w + (i + 0) * NDFF), c0);
            c1 = fmaf(xq[i + 1], __ldg(w + (i + 1) * NDFF), c1);
            c2 = fmaf(xq[i + 2], __ldg(w + (i + 2) * NDFF), c2);
            c3 = fmaf(xq[i + 3], __ldg(w + (i + 3) * NDFF), c3);
            c4 = fmaf(xq[i + 4], __ldg(w + (i + 4) * NDFF), c4);
            c5 = fmaf(xq[i + 5], __ldg(w + (i + 5) * NDFF), c5);
            c6 = fmaf(xq[i + 6], __ldg(w + (i + 6) * NDFF), c6);
            c7 = fmaf(xq[i + 7], __ldg(w + (i + 7) * NDFF), c7);
        }
        sh_p[d] = ((c0 + c1) + (c2 + c3)) + ((c4 + c5) + (c6 + c7));
    }
    __syncthreads();
    if (d < NDFF) {
        float hv = sh_p[d] + sh_p[d + 256] + b1[blk * NDFF + d];
        sh_h[d] = fmaxf(hv, 0.f);
    }
    __syncthreads();

    float acc = b2[blk * ND + d];
    {
        const float* w2 = W2 + (size_t)blk * NDFF * ND + d;
        float c0 = 0.f, c1 = 0.f, c2 = 0.f, c3 = 0.f;
        float c4 = 0.f, c5 = 0.f, c6 = 0.f, c7 = 0.f;
        #pragma unroll 4
        for (int j = 0; j < NDFF; j += 8) {
            c0 = fmaf(sh_h[j + 0], __ldg(w2 + (j + 0) * ND), c0);
            c1 = fmaf(sh_h[j + 1], __ldg(w2 + (j + 1) * ND), c1);
            c2 = fmaf(sh_h[j + 2], __ldg(w2 + (j + 2) * ND), c2);
            c3 = fmaf(sh_h[j + 3], __ldg(w2 + (j + 3) * ND), c3);
            c4 = fmaf(sh_h[j + 4], __ldg(w2 + (j + 4) * ND), c4);
            c5 = fmaf(sh_h[j + 5], __ldg(w2 + (j + 5) * ND), c5);
            c6 = fmaf(sh_h[j + 6], __ldg(w2 + (j + 6) * ND), c6);
            c7 = fmaf(sh_h[j + 7], __ldg(w2 + (j + 7) * ND), c7);
        }
        acc += ((c0 + c1) + (c2 + c3)) + ((c4 + c5) + (c6 + c7));
    }
    float x2 = qn1 + acc;

    float mu2  = block_sum_512(x2, red) * (1.0f / ND);
    float dev2 = x2 - mu2;
    float var2 = block_sum_512(dev2 * dev2, red) * (1.0f / (ND - 1));
    float qn2 = al2[blk * ND + d] * dev2 / (sqrtf(var2) + FEPS) + bi2[blk * ND + d];

    g_q[b * ND + d] = qn2;
    if (write_out) out[b * (2 * ND) + out_off + d] = qn2;
}

// ---------------- launch ----------------
extern "C" void kernel_launch(void* const* d_in, const int* in_sizes, int n_in,
                              void* d_out, int out_size) {
    const float* q   = (const float*)d_in[0];
    const float* k   = (const float*)d_in[1];
    const float* v   = (const float*)d_in[2];
    const float* W1  = (const float*)d_in[3];
    const float* b1  = (const float*)d_in[4];
    const float* W2  = (const float*)d_in[5];
    const float* b2  = (const float*)d_in[6];
    const float* al1 = (const float*)d_in[7];
    const float* bi1 = (const float*)d_in[8];
    const float* al2 = (const float*)d_in[9];
    const float* bi2 = (const float*)d_in[10];

    float* out_p = (float*)d_out;                 // (32, 1024)
    float* w_p   = (float*)d_out + NB * 2 * ND;   // (32, 2048, 6)

    initq_kernel<<<(NB * ND + 255) / 256, 256>>>(q);

    for (int blk = 0; blk < NBLK; blk++) {
        scores_kernel<<<(NB * NL / 2 * 32) / 256, 256>>>(k);
        softmax_kernel<<<NB, 512>>>(w_p, blk);
        apart_kernel<<<dim3(NCHUNK, NB), 256>>>(v);
        int wr = (blk == 2 || blk == 5) ? 1 : 0;
        int off = (blk == 5) ? ND : 0;
        tail_kernel<<<NB, 512>>>(W1, b1, W2, b2, al1, bi1, al2, bi2,
                                 out_p, blk, wr, off);
    }
}

// round 10
// speedup vs baseline: 2.4723x; 1.0364x over previous
#include <cuda_runtime.h>
#include <math.h>

#define NB   32
#define NL   2048
#define ND   512
#define NDFF 256
#define NBLK 6
#define FEPS 1e-6f
#define LCHUNK 64
#define NCHUNK (NL / LCHUNK)   // 32

// ---------------- device scratch (no allocations allowed) ----------------
__device__ float g_q[NB * ND];              // evolving query
__device__ float g_scores[NB * NL];         // raw scores
__device__ float g_s[NB * NL];              // softmax probs (contiguous)
__device__ float g_Apart[NB * NCHUNK * ND]; // partial attention outputs

// ---------------- helpers ----------------
__device__ __forceinline__ float block_sum_512(float v, float* red) {
    #pragma unroll
    for (int o = 16; o; o >>= 1) v += __shfl_xor_sync(0xffffffffu, v, o);
    int w = threadIdx.x >> 5;
    if ((threadIdx.x & 31) == 0) red[w] = v;
    __syncthreads();
    if (threadIdx.x < 16) {
        float t = red[threadIdx.x];
        #pragma unroll
        for (int o = 8; o; o >>= 1) t += __shfl_xor_sync(0xffffu, t, o);
        if (threadIdx.x == 0) red[0] = t;
    }
    __syncthreads();
    float r = red[0];
    __syncthreads();
    return r;
}

__device__ __forceinline__ float dot4(float4 a, float4 b, float acc) {
    acc = fmaf(a.x, b.x, acc);
    acc = fmaf(a.y, b.y, acc);
    acc = fmaf(a.z, b.z, acc);
    acc = fmaf(a.w, b.w, acc);
    return acc;
}

// ---------------- kernels ----------------
__global__ void initq_kernel(const float* __restrict__ q) {
    int i = blockIdx.x * blockDim.x + threadIdx.x;
    if (i < NB * ND) g_q[i] = q[i];
}

// scores: TWO rows per warp; 8 x 16B loads in flight per lane (R9-measured best)
__global__ void scores_kernel(const float* __restrict__ k) {
    int warp = (blockIdx.x * blockDim.x + threadIdx.x) >> 5;  // 0..NB*NL/2-1
    int lane = threadIdx.x & 31;
    if (warp >= NB * NL / 2) return;
    int r0 = warp * 2;            // rows r0, r0+1 (same batch: 2048 rows per b)
    int b = r0 >> 11;
    const float4* kA = reinterpret_cast<const float4*>(k + (size_t)r0 * ND) + lane;
    const float4* kB = reinterpret_cast<const float4*>(k + (size_t)(r0 + 1) * ND) + lane;
    const float4* q4 = reinterpret_cast<const float4*>(g_q + b * ND) + lane;

    float4 a0 = __ldcs(kA + 0);
    float4 a1 = __ldcs(kA + 32);
    float4 a2 = __ldcs(kA + 64);
    float4 a3 = __ldcs(kA + 96);
    float4 b0 = __ldcs(kB + 0);
    float4 b1 = __ldcs(kB + 32);
    float4 b2 = __ldcs(kB + 64);
    float4 b3 = __ldcs(kB + 96);
    float4 q0 = q4[0], q1 = q4[32], q2 = q4[64], q3 = q4[96];

    float accA = 0.f, accB = 0.f;
    accA = dot4(a0, q0, accA); accB = dot4(b0, q0, accB);
    accA = dot4(a1, q1, accA); accB = dot4(b1, q1, accB);
    accA = dot4(a2, q2, accA); accB = dot4(b2, q2, accB);
    accA = dot4(a3, q3, accA); accB = dot4(b3, q3, accB);

    #pragma unroll
    for (int o = 16; o; o >>= 1) {
        accA += __shfl_xor_sync(0xffffffffu, accA, o);
        accB += __shfl_xor_sync(0xffffffffu, accB, o);
    }
    if (lane == 0) {
        const float s = 0.04419417382415922f;   // 1/sqrt(512)
        g_scores[r0]     = accA * s;
        g_scores[r0 + 1] = accB * s;
    }
}

// softmax over L per batch; writes contiguous g_s and strided weights[:, :, blk]
__global__ void softmax_kernel(float* __restrict__ wout, int blk) {
    int b = blockIdx.x;
    int t = threadIdx.x;            // 512 threads
    __shared__ float red[16];
    const float* sc = g_scores + b * NL;

    float e[NL / 512];
    float m = -INFINITY;
    #pragma unroll
    for (int i = 0; i < NL / 512; i++) {
        e[i] = sc[t + i * 512];
        m = fmaxf(m, e[i]);
    }
    #pragma unroll
    for (int o = 16; o; o >>= 1) m = fmaxf(m, __shfl_xor_sync(0xffffffffu, m, o));
    int w = t >> 5;
    if ((t & 31) == 0) red[w] = m;
    __syncthreads();
    if (t < 16) {
        float x = red[t];
        #pragma unroll
        for (int o = 8; o; o >>= 1) x = fmaxf(x, __shfl_xor_sync(0xffffu, x, o));
        if (t == 0) red[0] = x;
    }
    __syncthreads();
    m = red[0];
    __syncthreads();

    float sum = 0.f;
    #pragma unroll
    for (int i = 0; i < NL / 512; i++) {
        e[i] = expf(e[i] - m);
        sum += e[i];
    }
    float tot = block_sum_512(sum, red);
    float inv = 1.0f / tot;

    #pragma unroll
    for (int i = 0; i < NL / 512; i++) {
        int l = t + i * 512;
        float sv = e[i] * inv;
        g_s[b * NL + l] = sv;
        wout[((size_t)b * NL + l) * NBLK + blk] = sv;
    }
}

// partial A (R3-measured best): one block per (l-chunk, b); 128 threads, float4
__global__ void apart_kernel(const float* __restrict__ v) {
    int c = blockIdx.x;     // 0..NCHUNK-1
    int b = blockIdx.y;     // 0..31
    int t = threadIdx.x;    // 0..127
    __shared__ float ss[LCHUNK];
    if (t < LCHUNK) ss[t] = g_s[b * NL + c * LCHUNK + t];
    __syncthreads();
    const float4* vp = reinterpret_cast<const float4*>(
        v + ((size_t)b * NL + (size_t)c * LCHUNK) * ND) + t;  // row stride ND/4=128
    float4 a0 = {0,0,0,0}, a1 = {0,0,0,0}, a2 = {0,0,0,0}, a3 = {0,0,0,0};
    #pragma unroll 4
    for (int l = 0; l < LCHUNK; l += 4) {
        float4 v0 = __ldcs(vp + (l + 0) * 128);
        float4 v1 = __ldcs(vp + (l + 1) * 128);
        float4 v2 = __ldcs(vp + (l + 2) * 128);
        float4 v3 = __ldcs(vp + (l + 3) * 128);
        float s0 = ss[l + 0], s1 = ss[l + 1], s2 = ss[l + 2], s3 = ss[l + 3];
        a0.x = fmaf(s0, v0.x, a0.x); a0.y = fmaf(s0, v0.y, a0.y);
        a0.z = fmaf(s0, v0.z, a0.z); a0.w = fmaf(s0, v0.w, a0.w);
        a1.x = fmaf(s1, v1.x, a1.x); a1.y = fmaf(s1, v1.y, a1.y);
        a1.z = fmaf(s1, v1.z, a1.z); a1.w = fmaf(s1, v1.w, a1.w);
        a2.x = fmaf(s2, v2.x, a2.x); a2.y = fmaf(s2, v2.y, a2.y);
        a2.z = fmaf(s2, v2.z, a2.z); a2.w = fmaf(s2, v2.w, a2.w);
        a3.x = fmaf(s3, v3.x, a3.x); a3.y = fmaf(s3, v3.y, a3.y);
        a3.z = fmaf(s3, v3.z, a3.z); a3.w = fmaf(s3, v3.w, a3.w);
    }
    float4 r;
    r.x = (a0.x + a1.x) + (a2.x + a3.x);
    r.y = (a0.y + a1.y) + (a2.y + a3.y);
    r.z = (a0.z + a1.z) + (a2.z + a3.z);
    r.w = (a0.w + a1.w) + (a2.w + a3.w);
    reinterpret_cast<float4*>(g_Apart + (b * NCHUNK + c) * ND)[t] = r;
}

// fused tail: reduce partials + residual + Norm1 + FF(relu) + FF2 + residual + Norm2
__global__ void tail_kernel(const float* __restrict__ W1, const float* __restrict__ b1,
                            const float* __restrict__ W2, const float* __restrict__ b2,
                            const float* __restrict__ al1, const float* __restrict__ bi1,
                            const float* __restrict__ al2, const float* __restrict__ bi2,
                            float* __restrict__ out, int blk, int write_out, int out_off) {
    int b = blockIdx.x;   // 32
    int d = threadIdx.x;  // 512
    __shared__ float red[16];
    __shared__ float sh_q[ND];
    __shared__ float sh_p[ND];
    __shared__ float sh_h[NDFF];

    float x = g_q[b * ND + d];
    #pragma unroll 8
    for (int c = 0; c < NCHUNK; c++) x += g_Apart[(b * NCHUNK + c) * ND + d];

    float mu  = block_sum_512(x, red) * (1.0f / ND);
    float dev = x - mu;
    float var = block_sum_512(dev * dev, red) * (1.0f / (ND - 1));
    float qn1 = al1[blk * ND + d] * dev / (sqrtf(var) + FEPS) + bi1[blk * ND + d];
    sh_q[d] = qn1;
    __syncthreads();

    {
        int j    = d & (NDFF - 1);
        int half = d >> 8;
        const float* w  = W1 + (size_t)blk * ND * NDFF + (size_t)(half * 256) * NDFF + j;
        const float* xq = sh_q + half * 256;
        float c0 = 0.f, c1 = 0.f, c2 = 0.f, c3 = 0.f;
        float c4 = 0.f, c5 = 0.f, c6 = 0.f, c7 = 0.f;
        #pragma unroll 4
        for (int i = 0; i < 256; i += 8) {
            c0 = fmaf(xq[i + 0], __ldg(w + (i + 0) * NDFF), c0);
            c1 = fmaf(xq[i + 1], __ldg(w + (i + 1) * NDFF), c1);
            c2 = fmaf(xq[i + 2], __ldg(w + (i + 2) * NDFF), c2);
            c3 = fmaf(xq[i + 3], __ldg(w + (i + 3) * NDFF), c3);
            c4 = fmaf(xq[i + 4], __ldg(w + (i + 4) * NDFF), c4);
            c5 = fmaf(xq[i + 5], __ldg(w + (i + 5) * NDFF), c5);
            c6 = fmaf(xq[i + 6], __ldg(w + (i + 6) * NDFF), c6);
            c7 = fmaf(xq[i + 7], __ldg(w + (i + 7) * NDFF), c7);
        }
        sh_p[d] = ((c0 + c1) + (c2 + c3)) + ((c4 + c5) + (c6 + c7));
    }
    __syncthreads();
    if (d < NDFF) {
        float hv = sh_p[d] + sh_p[d + 256] + b1[blk * NDFF + d];
        sh_h[d] = fmaxf(hv, 0.f);
    }
    __syncthreads();

    float acc = b2[blk * ND + d];
    {
        const float* w2 = W2 + (size_t)blk * NDFF * ND + d;
        float c0 = 0.f, c1 = 0.f, c2 = 0.f, c3 = 0.f;
        float c4 = 0.f, c5 = 0.f, c6 = 0.f, c7 = 0.f;
        #pragma unroll 4
        for (int j = 0; j < NDFF; j += 8) {
            c0 = fmaf(sh_h[j + 0], __ldg(w2 + (j + 0) * ND), c0);
            c1 = fmaf(sh_h[j + 1], __ldg(w2 + (j + 1) * ND), c1);
            c2 = fmaf(sh_h[j + 2], __ldg(w2 + (j + 2) * ND), c2);
            c3 = fmaf(sh_h[j + 3], __ldg(w2 + (j + 3) * ND), c3);
            c4 = fmaf(sh_h[j + 4], __ldg(w2 + (j + 4) * ND), c4);
            c5 = fmaf(sh_h[j + 5], __ldg(w2 + (j + 5) * ND), c5);
            c6 = fmaf(sh_h[j + 6], __ldg(w2 + (j + 6) * ND), c6);
            c7 = fmaf(sh_h[j + 7], __ldg(w2 + (j + 7) * ND), c7);
        }
        acc += ((c0 + c1) + (c2 + c3)) + ((c4 + c5) + (c6 + c7));
    }
    float x2 = qn1 + acc;

    float mu2  = block_sum_512(x2, red) * (1.0f / ND);
    float dev2 = x2 - mu2;
    float var2 = block_sum_512(dev2 * dev2, red) * (1.0f / (ND - 1));
    float qn2 = al2[blk * ND + d] * dev2 / (sqrtf(var2) + FEPS) + bi2[blk * ND + d];

    g_q[b * ND + d] = qn2;
    if (write_out) out[b * (2 * ND) + out_off + d] = qn2;
}

// ---------------- launch ----------------
extern "C" void kernel_launch(void* const* d_in, const int* in_sizes, int n_in,
                              void* d_out, int out_size) {
    const float* q   = (const float*)d_in[0];
    const float* k   = (const float*)d_in[1];
    const float* v   = (const float*)d_in[2];
    const float* W1  = (const float*)d_in[3];
    const float* b1  = (const float*)d_in[4];
    const float* W2  = (const float*)d_in[5];
    const float* b2  = (const float*)d_in[6];
    const float* al1 = (const float*)d_in[7];
    const float* bi1 = (const float*)d_in[8];
    const float* al2 = (const float*)d_in[9];
    const float* bi2 = (const float*)d_in[10];

    float* out_p = (float*)d_out;                 // (32, 1024)
    float* w_p   = (float*)d_out + NB * 2 * ND;   // (32, 2048, 6)

    initq_kernel<<<(NB * ND + 255) / 256, 256>>>(q);

    for (int blk = 0; blk < NBLK; blk++) {
        scores_kernel<<<(NB * NL / 2 * 32) / 256, 256>>>(k);
        softmax_kernel<<<NB, 512>>>(w_p, blk);
        apart_kernel<<<dim3(NCHUNK, NB), 128>>>(v);
        int wr = (blk == 2 || blk == 5) ? 1 : 0;
        int off = (blk == 5) ? ND : 0;
        tail_kernel<<<NB, 512>>>(W1, b1, W2, b2, al1, bi1, al2, bi2,
                                 out_p, blk, wr, off);
    }
}